// round 1
// baseline (speedup 1.0000x reference)
#include <cuda_runtime.h>
#include <math.h>

#define BB 16
#define SS 1024
#define DD 1024
#define HH 16
#define DH 64

// Scratch for Q, K, V in head-split layout [B, H, S, Dh] (64 MB each).
__device__ float g_q[BB * HH * SS * DH];
__device__ float g_k[BB * HH * SS * DH];
__device__ float g_v[BB * HH * SS * DH];

// ---------------------------------------------------------------------------
// QKV projection: Y = X @ W^T + b, X:[16384,1024] row-major, W:[1024,1024]
// row-major (row n = output feature n). Output written head-split into
// g_q / g_k / g_v per `which`.
// Tiling: BM=BN=128, BK=16, 256 threads, 8x8 register tile per thread.
// ---------------------------------------------------------------------------
__global__ __launch_bounds__(256)
void qkv_gemm(const float* __restrict__ X, const float* __restrict__ W,
              const float* __restrict__ bias, int which)
{
    __shared__ float sa[16][128];
    __shared__ float sb[16][128];

    float* __restrict__ Y = (which == 0) ? g_q : (which == 1) ? g_k : g_v;

    const int tid = threadIdx.x;
    const int m0  = blockIdx.y * 128;
    const int n0  = blockIdx.x * 128;

    // load indices: each thread loads two float4 from X and two from W
    const int r  = tid >> 2;            // 0..63
    const int kq = (tid & 3) * 4;       // 0,4,8,12

    const float* xp = X + (size_t)(m0 + r) * DD + kq;
    const float* wp = W + (size_t)(n0 + r) * DD + kq;

    // compute indices
    const int tm = (tid >> 4) * 8;      // 0..120
    const int tn = (tid & 15) * 8;      // 0..120

    float acc[8][8];
    #pragma unroll
    for (int i = 0; i < 8; i++)
        #pragma unroll
        for (int j = 0; j < 8; j++)
            acc[i][j] = 0.0f;

    for (int k0 = 0; k0 < DD; k0 += 16) {
        float4 a0 = *(const float4*)(xp + k0);
        float4 a1 = *(const float4*)(xp + k0 + (size_t)64 * DD);
        float4 b0 = *(const float4*)(wp + k0);
        float4 b1 = *(const float4*)(wp + k0 + (size_t)64 * DD);

        __syncthreads();   // previous iteration's compute reads done
        sa[kq+0][r]    = a0.x; sa[kq+1][r]    = a0.y; sa[kq+2][r]    = a0.z; sa[kq+3][r]    = a0.w;
        sa[kq+0][r+64] = a1.x; sa[kq+1][r+64] = a1.y; sa[kq+2][r+64] = a1.z; sa[kq+3][r+64] = a1.w;
        sb[kq+0][r]    = b0.x; sb[kq+1][r]    = b0.y; sb[kq+2][r]    = b0.z; sb[kq+3][r]    = b0.w;
        sb[kq+0][r+64] = b1.x; sb[kq+1][r+64] = b1.y; sb[kq+2][r+64] = b1.z; sb[kq+3][r+64] = b1.w;
        __syncthreads();

        #pragma unroll
        for (int kk = 0; kk < 16; kk++) {
            float4 af0 = *(const float4*)&sa[kk][tm];
            float4 af1 = *(const float4*)&sa[kk][tm + 4];
            float4 bf0 = *(const float4*)&sb[kk][tn];
            float4 bf1 = *(const float4*)&sb[kk][tn + 4];
            float av[8] = {af0.x, af0.y, af0.z, af0.w, af1.x, af1.y, af1.z, af1.w};
            float bv[8] = {bf0.x, bf0.y, bf0.z, bf0.w, bf1.x, bf1.y, bf1.z, bf1.w};
            #pragma unroll
            for (int i = 0; i < 8; i++)
                #pragma unroll
                for (int j = 0; j < 8; j++)
                    acc[i][j] += av[i] * bv[j];
        }
    }

    // Epilogue: bias add + head-split store Y[((b*16+h)*1024+s)*64 + d]
    #pragma unroll
    for (int i = 0; i < 8; i++) {
        int m  = m0 + tm + i;
        int b  = m >> 10;
        int s  = m & 1023;
        #pragma unroll
        for (int j = 0; j < 8; j++) {
            int n = n0 + tn + j;
            int h = n >> 6;
            int d = n & 63;
            Y[(((size_t)(b * HH + h) * SS + s) * DH) + d] = acc[i][j] + bias[n];
        }
    }
}

// ---------------------------------------------------------------------------
// Flash-style attention: one block = 128 query rows of one (b,h); one thread
// = one query row (q[64], o[64] in registers). KV streamed in tiles of 32
// rows through smem. Online softmax with registers-only scores s[32].
// ---------------------------------------------------------------------------
__global__ __launch_bounds__(128)
void attn_kernel(float* __restrict__ out)
{
    __shared__ float sk[32 * 64];
    __shared__ float sv[32 * 64];

    const int tid = threadIdx.x;
    const int row = blockIdx.x * 128 + tid;   // query index in S
    const int bh  = blockIdx.y;               // b*16 + h
    const int b   = bh >> 4;
    const int h   = bh & 15;

    const float* qrow = g_q + ((size_t)bh * SS + row) * DH;
    float q[64];
    #pragma unroll
    for (int dd = 0; dd < 16; dd++) {
        float4 t = *(const float4*)(qrow + dd * 4);
        q[4*dd+0] = t.x; q[4*dd+1] = t.y; q[4*dd+2] = t.z; q[4*dd+3] = t.w;
    }

    float o[64];
    #pragma unroll
    for (int d = 0; d < 64; d++) o[d] = 0.0f;
    float mval = -INFINITY;
    float lsum = 0.0f;

    const float* Kb = g_k + (size_t)bh * SS * DH;
    const float* Vb = g_v + (size_t)bh * SS * DH;

    for (int t0 = 0; t0 < SS; t0 += 32) {
        // cooperative tile load: 32 rows x 64 = 2048 contiguous floats each
        const float4* kp = (const float4*)(Kb + (size_t)t0 * DH);
        const float4* vp = (const float4*)(Vb + (size_t)t0 * DH);
        float4* sk4 = (float4*)sk;
        float4* sv4 = (float4*)sv;
        __syncthreads();
        #pragma unroll
        for (int i = 0; i < 4; i++) {
            sk4[tid + i * 128] = kp[tid + i * 128];
            sv4[tid + i * 128] = vp[tid + i * 128];
        }
        __syncthreads();

        // scores: s[j] = (q . K[j]) / 8
        float s[32];
        #pragma unroll
        for (int j = 0; j < 32; j++) {
            const float4* krow = (const float4*)(sk + j * 64);
            float a = 0.0f;
            #pragma unroll
            for (int dd = 0; dd < 16; dd++) {
                float4 kv = krow[dd];
                a += q[4*dd+0] * kv.x;
                a += q[4*dd+1] * kv.y;
                a += q[4*dd+2] * kv.z;
                a += q[4*dd+3] * kv.w;
            }
            s[j] = a * 0.125f;
        }

        // online softmax update
        float tmax = mval;
        #pragma unroll
        for (int j = 0; j < 32; j++) tmax = fmaxf(tmax, s[j]);
        float scale = __expf(mval - tmax);
        mval = tmax;
        lsum *= scale;
        #pragma unroll
        for (int d = 0; d < 64; d++) o[d] *= scale;
        #pragma unroll
        for (int j = 0; j < 32; j++) {
            float p = __expf(s[j] - mval);
            lsum += p;
            s[j] = p;
        }

        // o += P @ V
        #pragma unroll
        for (int j = 0; j < 32; j++) {
            const float4* vrow = (const float4*)(sv + j * 64);
            float p = s[j];
            #pragma unroll
            for (int dd = 0; dd < 16; dd++) {
                float4 vv = vrow[dd];
                o[4*dd+0] += p * vv.x;
                o[4*dd+1] += p * vv.y;
                o[4*dd+2] += p * vv.z;
                o[4*dd+3] += p * vv.w;
            }
        }
    }

    float inv = 1.0f / lsum;
    float* orow = out + ((size_t)(b * SS + row)) * DD + h * DH;
    #pragma unroll
    for (int dd = 0; dd < 16; dd++) {
        float4 t;
        t.x = o[4*dd+0] * inv;
        t.y = o[4*dd+1] * inv;
        t.z = o[4*dd+2] * inv;
        t.w = o[4*dd+3] * inv;
        *(float4*)(orow + dd * 4) = t;
    }
}

extern "C" void kernel_launch(void* const* d_in, const int* in_sizes, int n_in,
                              void* d_out, int out_size)
{
    const float* x  = (const float*)d_in[0];
    const float* Wq = (const float*)d_in[1];
    const float* bq = (const float*)d_in[2];
    const float* Wk = (const float*)d_in[3];
    const float* bk = (const float*)d_in[4];
    const float* Wv = (const float*)d_in[5];
    const float* bv = (const float*)d_in[6];
    float* out = (float*)d_out;

    dim3 gg(DD / 128, (BB * SS) / 128);   // (8, 128)
    qkv_gemm<<<gg, 256>>>(x, Wq, bq, 0);
    qkv_gemm<<<gg, 256>>>(x, Wk, bk, 1);
    qkv_gemm<<<gg, 256>>>(x, Wv, bv, 2);

    dim3 ga(SS / 128, BB * HH);           // (8, 256)
    attn_kernel<<<ga, 128>>>(out);
}

// round 2
// speedup vs baseline: 3.6676x; 3.6676x over previous
#include <cuda_runtime.h>
#include <math.h>

#define BB 16
#define SS 1024
#define DD 1024
#define HH 16
#define DH 64

// Scratch for Q, K, V in head-split layout [B, H, S, Dh] (64 MB each).
__device__ float g_q[BB * HH * SS * DH];
__device__ float g_k[BB * HH * SS * DH];
__device__ float g_v[BB * HH * SS * DH];

// ---------------------------------------------------------------------------
// helpers
// ---------------------------------------------------------------------------
__device__ __forceinline__ float to_tf32(float x) {
    float r;
    asm("cvt.rna.tf32.f32 %0, %1;" : "=f"(r) : "f"(x));
    return r;
}

// d += a @ b  (m16n8k8 tf32, fp32 accum)
__device__ __forceinline__ void mma_tf32(float* d, const unsigned* a, const unsigned* b) {
    asm volatile(
        "mma.sync.aligned.m16n8k8.row.col.f32.tf32.tf32.f32 "
        "{%0,%1,%2,%3},{%4,%5,%6,%7},{%8,%9},{%0,%1,%2,%3};"
        : "+f"(d[0]), "+f"(d[1]), "+f"(d[2]), "+f"(d[3])
        : "r"(a[0]), "r"(a[1]), "r"(a[2]), "r"(a[3]), "r"(b[0]), "r"(b[1]));
}

// ---------------------------------------------------------------------------
// QKV projection: Y = X @ W^T + b.  X:[16384,1024] rm, W:[1024,1024] rm
// (row n = feature n, so W row-major == B col-major [K,N] for mma).
// BM=BN=128, BK=32, 256 threads (8 warps as 4x2), warp tile 32x64.
// ---------------------------------------------------------------------------
__global__ __launch_bounds__(256)
void qkv_gemm(const float* __restrict__ X, const float* __restrict__ W,
              const float* __restrict__ bias, int which)
{
    __shared__ float sa[128][36];   // [m][k], pad->stride 36
    __shared__ float sb[128][36];   // [n][k]

    float* __restrict__ Y = (which == 0) ? g_q : (which == 1) ? g_k : g_v;

    const int tid  = threadIdx.x;
    const int lane = tid & 31;
    const int warp = tid >> 5;
    const int wm   = (warp & 3) * 32;    // warp row base
    const int wn   = (warp >> 2) * 64;   // warp col base
    const int m0   = blockIdx.y * 128;
    const int n0   = blockIdx.x * 128;

    // gmem load mapping: 128 rows x 8 float4 per tile side; 256 thr -> 4 rows each
    const int lr = tid >> 3;       // 0..31
    const int lc = (tid & 7) * 4;  // 0,4,...,28

    float acc[2][8][4];
    #pragma unroll
    for (int i = 0; i < 2; i++)
        #pragma unroll
        for (int j = 0; j < 8; j++)
            #pragma unroll
            for (int c = 0; c < 4; c++) acc[i][j][c] = 0.0f;

    const int r4 = lane >> 2;   // 0..7
    const int c4 = lane & 3;    // 0..3

    for (int k0 = 0; k0 < DD; k0 += 32) {
        float4 va[4], vb[4];
        #pragma unroll
        for (int i = 0; i < 4; i++) {
            va[i] = *(const float4*)(X + (size_t)(m0 + lr + 32 * i) * DD + k0 + lc);
            vb[i] = *(const float4*)(W + (size_t)(n0 + lr + 32 * i) * DD + k0 + lc);
        }
        __syncthreads();
        #pragma unroll
        for (int i = 0; i < 4; i++) {
            sa[lr + 32 * i][lc + 0] = to_tf32(va[i].x);
            sa[lr + 32 * i][lc + 1] = to_tf32(va[i].y);
            sa[lr + 32 * i][lc + 2] = to_tf32(va[i].z);
            sa[lr + 32 * i][lc + 3] = to_tf32(va[i].w);
            sb[lr + 32 * i][lc + 0] = to_tf32(vb[i].x);
            sb[lr + 32 * i][lc + 1] = to_tf32(vb[i].y);
            sb[lr + 32 * i][lc + 2] = to_tf32(vb[i].z);
            sb[lr + 32 * i][lc + 3] = to_tf32(vb[i].w);
        }
        __syncthreads();

        #pragma unroll
        for (int ks = 0; ks < 4; ks++) {
            const int kk = ks * 8;
            unsigned af[2][4], bf[8][2];
            #pragma unroll
            for (int mt = 0; mt < 2; mt++) {
                const int rb = wm + mt * 16;
                af[mt][0] = __float_as_uint(sa[rb + r4    ][kk + c4    ]);
                af[mt][1] = __float_as_uint(sa[rb + r4 + 8][kk + c4    ]);
                af[mt][2] = __float_as_uint(sa[rb + r4    ][kk + c4 + 4]);
                af[mt][3] = __float_as_uint(sa[rb + r4 + 8][kk + c4 + 4]);
            }
            #pragma unroll
            for (int nt = 0; nt < 8; nt++) {
                const int cb = wn + nt * 8;
                bf[nt][0] = __float_as_uint(sb[cb + r4][kk + c4    ]);
                bf[nt][1] = __float_as_uint(sb[cb + r4][kk + c4 + 4]);
            }
            #pragma unroll
            for (int mt = 0; mt < 2; mt++)
                #pragma unroll
                for (int nt = 0; nt < 8; nt++)
                    mma_tf32(acc[mt][nt], af[mt], bf[nt]);
        }
    }

    // Epilogue: bias + head-split scatter. c0/c1: (row, 2c/2c+1); c2/c3: row+8
    #pragma unroll
    for (int mt = 0; mt < 2; mt++) {
        const int mA = m0 + wm + mt * 16 + r4;
        const int mB = mA + 8;
        const int bA = mA >> 10, sA = mA & 1023;
        const int bB = mB >> 10, sB = mB & 1023;
        #pragma unroll
        for (int nt = 0; nt < 8; nt++) {
            const int col = n0 + wn + nt * 8 + 2 * c4;
            const int h = col >> 6, d = col & 63;
            const float b0 = bias[col], b1 = bias[col + 1];
            float2 vA = make_float2(acc[mt][nt][0] + b0, acc[mt][nt][1] + b1);
            float2 vB = make_float2(acc[mt][nt][2] + b0, acc[mt][nt][3] + b1);
            *(float2*)(Y + (((size_t)(bA * HH + h) * SS + sA) * DH) + d) = vA;
            *(float2*)(Y + (((size_t)(bB * HH + h) * SS + sB) * DH) + d) = vB;
        }
    }
}

// ---------------------------------------------------------------------------
// Flash attention with tf32 mma. Block: 128 thr (4 warps), BR=64 (16 q rows
// per warp), BC=32 KV tiles, Dh=64. Online softmax on C fragments.
// ---------------------------------------------------------------------------
__global__ __launch_bounds__(128)
void attn_kernel(float* __restrict__ out)
{
    __shared__ float sk[32][68];        // [kv][dh]
    __shared__ float sv[32][72];        // [kv][dh]
    __shared__ float sp[4][16][68];     // per-warp: Q staging, then P tile

    const int tid  = threadIdx.x;
    const int lane = tid & 31;
    const int warp = tid >> 5;
    const int bh   = blockIdx.y;
    const int b    = bh >> 4;
    const int h    = bh & 15;
    const int qrow0 = blockIdx.x * 64 + warp * 16;   // warp's first q row

    const int r4 = lane >> 2;   // 0..7
    const int c4 = lane & 3;    // 0..3

    const float* Qb = g_q + (size_t)bh * SS * DH;
    const float* Kb = g_k + (size_t)bh * SS * DH;
    const float* Vb = g_v + (size_t)bh * SS * DH;

    // --- stage Q (scaled by 1/8, tf32-rounded) into sp[warp], load fragments
    {
        #pragma unroll
        for (int i = 0; i < 8; i++) {
            const int idx = lane + i * 32;          // 0..255
            const int row = idx >> 4;               // 0..15
            const int cc  = (idx & 15) * 4;
            float4 t = *(const float4*)(Qb + (size_t)(qrow0 + row) * DH + cc);
            sp[warp][row][cc + 0] = to_tf32(t.x * 0.125f);
            sp[warp][row][cc + 1] = to_tf32(t.y * 0.125f);
            sp[warp][row][cc + 2] = to_tf32(t.z * 0.125f);
            sp[warp][row][cc + 3] = to_tf32(t.w * 0.125f);
        }
    }
    __syncwarp();
    unsigned qa[8][4];
    #pragma unroll
    for (int kt = 0; kt < 8; kt++) {
        qa[kt][0] = __float_as_uint(sp[warp][r4    ][kt * 8 + c4    ]);
        qa[kt][1] = __float_as_uint(sp[warp][r4 + 8][kt * 8 + c4    ]);
        qa[kt][2] = __float_as_uint(sp[warp][r4    ][kt * 8 + c4 + 4]);
        qa[kt][3] = __float_as_uint(sp[warp][r4 + 8][kt * 8 + c4 + 4]);
    }
    __syncwarp();

    float o[8][4];
    #pragma unroll
    for (int nt = 0; nt < 8; nt++)
        #pragma unroll
        for (int c = 0; c < 4; c++) o[nt][c] = 0.0f;
    float m0v = -INFINITY, m1v = -INFINITY;
    float l0 = 0.0f, l1 = 0.0f;

    for (int t0 = 0; t0 < SS; t0 += 32) {
        __syncthreads();
        // cooperative load K,V tile (tf32-rounded): 32 rows x 16 float4
        #pragma unroll
        for (int i = 0; i < 4; i++) {
            const int idx = tid + i * 128;          // 0..511
            const int row = idx >> 4;               // 0..31
            const int cc  = (idx & 15) * 4;
            float4 kt4 = *(const float4*)(Kb + (size_t)(t0 + row) * DH + cc);
            float4 vt4 = *(const float4*)(Vb + (size_t)(t0 + row) * DH + cc);
            sk[row][cc + 0] = to_tf32(kt4.x); sk[row][cc + 1] = to_tf32(kt4.y);
            sk[row][cc + 2] = to_tf32(kt4.z); sk[row][cc + 3] = to_tf32(kt4.w);
            sv[row][cc + 0] = to_tf32(vt4.x); sv[row][cc + 1] = to_tf32(vt4.y);
            sv[row][cc + 2] = to_tf32(vt4.z); sv[row][cc + 3] = to_tf32(vt4.w);
        }
        __syncthreads();

        // S = Q @ K^T  : 4 n-tiles (kv) x 8 k-steps (dh)
        float s[4][4];
        #pragma unroll
        for (int nt = 0; nt < 4; nt++) {
            #pragma unroll
            for (int c = 0; c < 4; c++) s[nt][c] = 0.0f;
            #pragma unroll
            for (int kt = 0; kt < 8; kt++) {
                unsigned bf[2];
                bf[0] = __float_as_uint(sk[nt * 8 + r4][kt * 8 + c4    ]);
                bf[1] = __float_as_uint(sk[nt * 8 + r4][kt * 8 + c4 + 4]);
                mma_tf32(s[nt], qa[kt], bf);
            }
        }

        // online softmax (rows r4 and r4+8 within the warp tile)
        float tm0 = -INFINITY, tm1 = -INFINITY;
        #pragma unroll
        for (int nt = 0; nt < 4; nt++) {
            tm0 = fmaxf(tm0, fmaxf(s[nt][0], s[nt][1]));
            tm1 = fmaxf(tm1, fmaxf(s[nt][2], s[nt][3]));
        }
        tm0 = fmaxf(tm0, __shfl_xor_sync(0xffffffffu, tm0, 1));
        tm0 = fmaxf(tm0, __shfl_xor_sync(0xffffffffu, tm0, 2));
        tm1 = fmaxf(tm1, __shfl_xor_sync(0xffffffffu, tm1, 1));
        tm1 = fmaxf(tm1, __shfl_xor_sync(0xffffffffu, tm1, 2));

        const float mn0 = fmaxf(m0v, tm0);
        const float mn1 = fmaxf(m1v, tm1);
        const float sc0 = __expf(m0v - mn0);
        const float sc1 = __expf(m1v - mn1);
        m0v = mn0; m1v = mn1;

        float ps0 = 0.0f, ps1 = 0.0f;
        #pragma unroll
        for (int nt = 0; nt < 4; nt++) {
            s[nt][0] = __expf(s[nt][0] - mn0);
            s[nt][1] = __expf(s[nt][1] - mn0);
            s[nt][2] = __expf(s[nt][2] - mn1);
            s[nt][3] = __expf(s[nt][3] - mn1);
            ps0 += s[nt][0] + s[nt][1];
            ps1 += s[nt][2] + s[nt][3];
        }
        ps0 += __shfl_xor_sync(0xffffffffu, ps0, 1);
        ps0 += __shfl_xor_sync(0xffffffffu, ps0, 2);
        ps1 += __shfl_xor_sync(0xffffffffu, ps1, 1);
        ps1 += __shfl_xor_sync(0xffffffffu, ps1, 2);
        l0 = l0 * sc0 + ps0;
        l1 = l1 * sc1 + ps1;

        #pragma unroll
        for (int nt = 0; nt < 8; nt++) {
            o[nt][0] *= sc0; o[nt][1] *= sc0;
            o[nt][2] *= sc1; o[nt][3] *= sc1;
        }

        // write P to warp-private smem (tf32 rounded), reload as A fragments
        #pragma unroll
        for (int nt = 0; nt < 4; nt++) {
            float2 pA = make_float2(to_tf32(s[nt][0]), to_tf32(s[nt][1]));
            float2 pB = make_float2(to_tf32(s[nt][2]), to_tf32(s[nt][3]));
            *(float2*)&sp[warp][r4    ][nt * 8 + 2 * c4] = pA;
            *(float2*)&sp[warp][r4 + 8][nt * 8 + 2 * c4] = pB;
        }
        __syncwarp();

        // O += P @ V : 4 k-steps (kv) x 8 n-tiles (dh)
        unsigned pa[4][4];
        #pragma unroll
        for (int kt = 0; kt < 4; kt++) {
            pa[kt][0] = __float_as_uint(sp[warp][r4    ][kt * 8 + c4    ]);
            pa[kt][1] = __float_as_uint(sp[warp][r4 + 8][kt * 8 + c4    ]);
            pa[kt][2] = __float_as_uint(sp[warp][r4    ][kt * 8 + c4 + 4]);
            pa[kt][3] = __float_as_uint(sp[warp][r4 + 8][kt * 8 + c4 + 4]);
        }
        #pragma unroll
        for (int nt = 0; nt < 8; nt++) {
            #pragma unroll
            for (int kt = 0; kt < 4; kt++) {
                unsigned bf[2];
                bf[0] = __float_as_uint(sv[kt * 8 + c4    ][nt * 8 + r4]);
                bf[1] = __float_as_uint(sv[kt * 8 + c4 + 4][nt * 8 + r4]);
                mma_tf32(o[nt], pa[kt], bf);
            }
        }
        __syncwarp();
    }

    // epilogue: normalize and store (out[(b*S + s)*D + h*64 + d])
    const float inv0 = 1.0f / l0;
    const float inv1 = 1.0f / l1;
    const int rA = qrow0 + r4;
    const int rB = rA + 8;
    float* oA = out + ((size_t)(b * SS + rA)) * DD + h * DH;
    float* oB = out + ((size_t)(b * SS + rB)) * DD + h * DH;
    #pragma unroll
    for (int nt = 0; nt < 8; nt++) {
        const int d = nt * 8 + 2 * c4;
        *(float2*)(oA + d) = make_float2(o[nt][0] * inv0, o[nt][1] * inv0);
        *(float2*)(oB + d) = make_float2(o[nt][2] * inv1, o[nt][3] * inv1);
    }
}

extern "C" void kernel_launch(void* const* d_in, const int* in_sizes, int n_in,
                              void* d_out, int out_size)
{
    const float* x  = (const float*)d_in[0];
    const float* Wq = (const float*)d_in[1];
    const float* bq = (const float*)d_in[2];
    const float* Wk = (const float*)d_in[3];
    const float* bk = (const float*)d_in[4];
    const float* Wv = (const float*)d_in[5];
    const float* bv = (const float*)d_in[6];
    float* out = (float*)d_out;

    dim3 gg(DD / 128, (BB * SS) / 128);   // (8, 128)
    qkv_gemm<<<gg, 256>>>(x, Wq, bq, 0);
    qkv_gemm<<<gg, 256>>>(x, Wk, bk, 1);
    qkv_gemm<<<gg, 256>>>(x, Wv, bv, 2);

    dim3 ga(SS / 64, BB * HH);            // (16, 256)
    attn_kernel<<<ga, 128>>>(out);
}